// round 5
// baseline (speedup 1.0000x reference)
#include <cuda_runtime.h>
#include <cstdint>

#define CNT_BLOCKS 16
#define NTHR 256

// Single packed accumulator: c0 bits[0:20), c2 bits[20:40), done bits[44:64).
// Zero at module load; finisher resets it each launch -> graph-replay safe.
__device__ unsigned long long g_acc = 0ull;
// g_cos[0..2] in one 16B segment for a single-LDG read by the finisher.
__device__ __align__(16) float g_cos[4];

#define DONE_ONE (1ull << 44)

__global__ void __launch_bounds__(NTHR, 1)
fused_kernel(const float* __restrict__ t1,
             const float* __restrict__ t2,
             const int* __restrict__ labels,
             int n, int d,
             float* __restrict__ out) {
    const int nb = gridDim.x;                  // CNT_BLOCKS + 1
    const bool cos_block = (blockIdx.x == nb - 1);
    const int wid = threadIdx.x >> 5;
    const int lane = threadIdx.x & 31;

    unsigned long long my_contrib;

    if (cos_block) {
        // labels in {0,1,2} and reference gathers rows BY LABEL VALUE,
        // so only rows 0..2 are ever used. Warp j computes cos(row j).
        if (wid < 3) {
            const float4* a = (const float4*)(t1 + (size_t)wid * d);
            const float4* b = (const float4*)(t2 + (size_t)wid * d);
            const int d4 = d >> 2;             // 128
            float dot = 0.f, na = 0.f, nbb = 0.f;
            #pragma unroll 4
            for (int i = lane; i < d4; i += 32) {
                float4 x = a[i], y = b[i];
                dot += x.x * y.x + x.y * y.y + x.z * y.z + x.w * y.w;
                na  += x.x * x.x + x.y * x.y + x.z * x.z + x.w * x.w;
                nbb += y.x * y.x + y.y * y.y + y.z * y.z + y.w * y.w;
            }
            #pragma unroll
            for (int off = 16; off > 0; off >>= 1) {
                dot += __shfl_down_sync(0xffffffffu, dot, off);
                na  += __shfl_down_sync(0xffffffffu, na, off);
                nbb += __shfl_down_sync(0xffffffffu, nbb, off);
            }
            if (lane == 0) {
                float denom = fmaxf(sqrtf(na) * sqrtf(nbb), 1e-8f);
                g_cos[wid] = dot / denom;
            }
        }
        my_contrib = DONE_ONE;
    } else {
        // 16 count blocks x 256 threads x 4 int4 = 65536 labels exactly.
        const int n4 = n >> 2;
        const int stride = (nb - 1) * NTHR;
        int c0 = 0, c2 = 0;
        const int4* l4 = (const int4*)labels;
        #pragma unroll 4
        for (int i = blockIdx.x * NTHR + threadIdx.x; i < n4; i += stride) {
            int4 v = l4[i];
            c0 += (v.x == 0) + (v.y == 0) + (v.z == 0) + (v.w == 0);
            c2 += (v.x == 2) + (v.y == 2) + (v.z == 2) + (v.w == 2);
        }
        if (blockIdx.x == 0) {                 // tail if n % 4 != 0
            for (int i = (n4 << 2) + threadIdx.x; i < n; i += NTHR) {
                int l = labels[i];
                c0 += (l == 0);
                c2 += (l == 2);
            }
        }
        #pragma unroll
        for (int off = 16; off > 0; off >>= 1) {
            c0 += __shfl_down_sync(0xffffffffu, c0, off);
            c2 += __shfl_down_sync(0xffffffffu, c2, off);
        }
        __shared__ int s0[NTHR / 32];
        __shared__ int s2[NTHR / 32];
        if (lane == 0) { s0[wid] = c0; s2[wid] = c2; }
        __syncthreads();
        int t0 = 0, t2v = 0;
        if (threadIdx.x == 0) {
            #pragma unroll
            for (int w = 0; w < NTHR / 32; ++w) { t0 += s0[w]; t2v += s2[w]; }
        }
        my_contrib = (unsigned long long)t0
                   | ((unsigned long long)t2v << 20)
                   | DONE_ONE;
    }

    // Publish this block's shared-state writes, then one atomic carries
    // counts + done-ticket together; its return value hands the finisher
    // the complete counts with no extra global read.
    __threadfence();
    __syncthreads();
    if (threadIdx.x == 0) {
        unsigned long long old = atomicAdd(&g_acc, my_contrib);
        unsigned long long total = old + my_contrib;
        if ((total >> 44) == (unsigned long long)nb) {
            int c0 = (int)(total & 0xFFFFFull);
            int c2 = (int)((total >> 20) & 0xFFFFFull);
            int c1 = n - c0 - c2;
            // One 16B volatile load for all three cosines (PTX: no float4
            // volatile copy-ctor in C++).
            float cx, cy, cz, cw;
            asm volatile("ld.volatile.global.v4.f32 {%0,%1,%2,%3}, [%4];"
                         : "=f"(cx), "=f"(cy), "=f"(cz), "=f"(cw)
                         : "l"(g_cos));
            float totalf = (float)c0 * (1.0f - cx)
                         + (float)c2 * (1.0f - cz)
                         + (float)c1 * fabsf(cy);
            out[0] = totalf / (float)n;
            // Reset for the next graph replay (all blocks already arrived).
            *(volatile unsigned long long*)&g_acc = 0ull;
            __threadfence();
        }
    }
}

extern "C" void kernel_launch(void* const* d_in, const int* in_sizes, int n_in,
                              void* d_out, int out_size) {
    const float* t1 = (const float*)d_in[0];
    const float* t2 = (const float*)d_in[1];
    const int* labels = (const int*)d_in[2];
    float* out = (float*)d_out;

    int n = in_sizes[2];          // 65536 labels
    int d = in_sizes[0] / n;      // 512

    fused_kernel<<<CNT_BLOCKS + 1, NTHR>>>(t1, t2, labels, n, d, out);
}

// round 6
// speedup vs baseline: 1.2651x; 1.2651x over previous
#include <cuda_runtime.h>
#include <cstdint>

#define CNT_BLOCKS 16
#define NTHR 256

// Packed accumulator: c0 bits[0:20), c2 bits[20:40), done bits[40:64).
// Zero at module load; the cos/finisher block resets it each launch after all
// count blocks have arrived -> graph-replay deterministic.
__device__ unsigned long long g_acc = 0ull;

#define DONE_ONE (1ull << 40)

__global__ void __launch_bounds__(NTHR, 1)
fused_kernel(const float* __restrict__ t1,
             const float* __restrict__ t2,
             const int* __restrict__ labels,
             int n, int d,
             float* __restrict__ out) {
    const int wid = threadIdx.x >> 5;
    const int lane = threadIdx.x & 31;

    if (blockIdx.x == CNT_BLOCKS) {
        // ---- cosine + finisher block ----
        // labels in {0,1,2}; reference gathers rows BY LABEL VALUE, so only
        // rows 0..2 of t1/t2 matter. Warp j computes cos(row j).
        __shared__ float s_cos[3];
        if (wid < 3) {
            const float4* a = (const float4*)(t1 + (size_t)wid * d);
            const float4* b = (const float4*)(t2 + (size_t)wid * d);
            const int d4 = d >> 2;             // 128
            float dot = 0.f, na = 0.f, nbb = 0.f;
            #pragma unroll 4
            for (int i = lane; i < d4; i += 32) {
                float4 x = a[i], y = b[i];
                dot += x.x * y.x + x.y * y.y + x.z * y.z + x.w * y.w;
                na  += x.x * x.x + x.y * x.y + x.z * x.z + x.w * x.w;
                nbb += y.x * y.x + y.y * y.y + y.z * y.z + y.w * y.w;
            }
            #pragma unroll
            for (int off = 16; off > 0; off >>= 1) {
                dot += __shfl_down_sync(0xffffffffu, dot, off);
                na  += __shfl_down_sync(0xffffffffu, na, off);
                nbb += __shfl_down_sync(0xffffffffu, nbb, off);
            }
            if (lane == 0) {
                float denom = fmaxf(sqrtf(na) * sqrtf(nbb), 1e-8f);
                s_cos[wid] = dot / denom;
            }
        }
        __syncthreads();
        if (threadIdx.x == 0) {
            // Spin until all count blocks have posted. They run 1 coalesced
            // int4 load + ballots, so they normally beat this block here:
            // the first poll should already succeed.
            unsigned long long v;
            do {
                asm volatile("ld.volatile.global.u64 %0, [%1];"
                             : "=l"(v) : "l"(&g_acc));
            } while ((v >> 40) != (unsigned long long)CNT_BLOCKS);

            int c0 = (int)(v & 0xFFFFFull);
            int c2 = (int)((v >> 20) & 0xFFFFFull);
            int c1 = n - c0 - c2;
            float cos0 = s_cos[0], cos1 = s_cos[1], cos2 = s_cos[2];
            float total = (float)c0 * (1.0f - cos0)
                        + (float)c2 * (1.0f - cos2)
                        + (float)c1 * fabsf(cos1);
            out[0] = total / (float)n;
            // Reset for next graph replay (all arrivals already happened;
            // kernel boundary orders this before next launch's atomics).
            *(volatile unsigned long long*)&g_acc = 0ull;
        }
    } else {
        // ---- count blocks: 16 x 256 threads x one int4 = 65536 labels ----
        const int n4 = n >> 2;
        const int stride = CNT_BLOCKS * NTHR;
        int c0 = 0, c2 = 0;
        const int4* l4 = (const int4*)labels;
        #pragma unroll 4
        for (int i = blockIdx.x * NTHR + threadIdx.x; i < n4; i += stride) {
            int4 v = l4[i];
            // Per-warp counts via ballot+popc: no serial shuffle chain.
            c0 += __popc(__ballot_sync(0xffffffffu, v.x == 0))
                + __popc(__ballot_sync(0xffffffffu, v.y == 0))
                + __popc(__ballot_sync(0xffffffffu, v.z == 0))
                + __popc(__ballot_sync(0xffffffffu, v.w == 0));
            c2 += __popc(__ballot_sync(0xffffffffu, v.x == 2))
                + __popc(__ballot_sync(0xffffffffu, v.y == 2))
                + __popc(__ballot_sync(0xffffffffu, v.z == 2))
                + __popc(__ballot_sync(0xffffffffu, v.w == 2));
        }
        if (blockIdx.x == 0) {                 // tail if n % 4 != 0
            for (int i = (n4 << 2) + threadIdx.x; i < n; i += NTHR) {
                int l = labels[i];
                c0 += __popc(__ballot_sync(__activemask(), l == 0)) == 0 ? 0 : (l == 0);
                c2 += (l == 2);
            }
        }
        // c0/c2 are warp-uniform (ballot results); lane 0 of each warp posts.
        __shared__ int s0[NTHR / 32];
        __shared__ int s2[NTHR / 32];
        if (lane == 0) { s0[wid] = c0; s2[wid] = c2; }
        __syncthreads();
        if (threadIdx.x == 0) {
            int t0 = 0, t2v = 0;
            #pragma unroll
            for (int w = 0; w < NTHR / 32; ++w) { t0 += s0[w]; t2v += s2[w]; }
            unsigned long long contrib = (unsigned long long)t0
                                       | ((unsigned long long)t2v << 20)
                                       | DONE_ONE;
            // Relaxed is fine: the whole contribution is inside the atomic.
            atomicAdd(&g_acc, contrib);
        }
    }
}

extern "C" void kernel_launch(void* const* d_in, const int* in_sizes, int n_in,
                              void* d_out, int out_size) {
    const float* t1 = (const float*)d_in[0];
    const float* t2 = (const float*)d_in[1];
    const int* labels = (const int*)d_in[2];
    float* out = (float*)d_out;

    int n = in_sizes[2];          // 65536 labels
    int d = in_sizes[0] / n;      // 512

    fused_kernel<<<CNT_BLOCKS + 1, NTHR>>>(t1, t2, labels, n, d, out);
}

// round 7
// speedup vs baseline: 1.3140x; 1.0386x over previous
#include <cuda_runtime.h>
#include <cstdint>

#define CNT_BLOCKS 16
#define NTHR 256
#define N_ACC 4                 // accumulators, 256B apart (distinct LTS slices)
#define BLKS_PER_ACC (CNT_BLOCKS / N_ACC)

// 4 packed accumulators: c0 bits[0:20), c2 bits[20:40), done bits[40:64).
// Zero at module load; the cos block's warp-3 lanes reset each one after its
// done-count hits BLKS_PER_ACC -> graph-replay deterministic.
__device__ unsigned long long g_acc[N_ACC * 32];   // stride 32 u64 = 256B

#define DONE_ONE (1ull << 40)
#define LOW40 ((1ull << 40) - 1ull)

__global__ void __launch_bounds__(NTHR, 1)
fused_kernel(const float* __restrict__ t1,
             const float* __restrict__ t2,
             const int* __restrict__ labels,
             int n, int d,
             float* __restrict__ out) {
    const int wid = threadIdx.x >> 5;
    const int lane = threadIdx.x & 31;

    if (blockIdx.x == CNT_BLOCKS) {
        // ---- cosine + finisher block ----
        // labels in {0,1,2}; reference gathers rows BY LABEL VALUE, so only
        // rows 0..2 of t1/t2 matter. Warp j (j<3) computes cos(row j).
        // Warp 3 polls the count accumulators IN PARALLEL, hiding the L2
        // round-trip under the cosine computation.
        __shared__ float s_cos[3];
        __shared__ int s_c0, s_c2;

        if (wid < 3) {
            const float4* a = (const float4*)(t1 + (size_t)wid * d);
            const float4* b = (const float4*)(t2 + (size_t)wid * d);
            const int d4 = d >> 2;             // 128
            float dot = 0.f, na = 0.f, nbb = 0.f;
            #pragma unroll 4
            for (int i = lane; i < d4; i += 32) {
                float4 x = a[i], y = b[i];
                dot += x.x * y.x + x.y * y.y + x.z * y.z + x.w * y.w;
                na  += x.x * x.x + x.y * x.y + x.z * x.z + x.w * x.w;
                nbb += y.x * y.x + y.y * y.y + y.z * y.z + y.w * y.w;
            }
            #pragma unroll
            for (int off = 16; off > 0; off >>= 1) {
                dot += __shfl_down_sync(0xffffffffu, dot, off);
                na  += __shfl_down_sync(0xffffffffu, na, off);
                nbb += __shfl_down_sync(0xffffffffu, nbb, off);
            }
            if (lane == 0) {
                float denom = fmaxf(sqrtf(na) * sqrtf(nbb), 1e-8f);
                s_cos[wid] = dot / denom;
            }
        } else if (wid == 3 && lane < N_ACC) {
            unsigned long long* addr = &g_acc[lane * 32];
            unsigned long long v;
            do {
                asm volatile("ld.volatile.global.u64 %0, [%1];"
                             : "=l"(v) : "l"(addr));
            } while ((v >> 40) != (unsigned long long)BLKS_PER_ACC);
            // Reset own accumulator for the next replay (all arrivals done).
            *(volatile unsigned long long*)addr = 0ull;
            // Sum packed counts across the 4 lanes (fields can't overflow:
            // totals < 2^17 in 20-bit fields).
            unsigned long long lo = v & LOW40;
            lo += __shfl_down_sync(0xFu, lo, 2, 4);
            lo += __shfl_down_sync(0xFu, lo, 1, 4);
            if (lane == 0) {
                s_c0 = (int)(lo & 0xFFFFFull);
                s_c2 = (int)((lo >> 20) & 0xFFFFFull);
            }
        }
        __syncthreads();
        if (threadIdx.x == 0) {
            int c0 = s_c0, c2 = s_c2;
            int c1 = n - c0 - c2;
            float total = (float)c0 * (1.0f - s_cos[0])
                        + (float)c2 * (1.0f - s_cos[2])
                        + (float)c1 * fabsf(s_cos[1]);
            out[0] = total / (float)n;
        }
    } else {
        // ---- count blocks: 16 x 256 threads x 4 int4 = 65536 labels ----
        const int n4 = n >> 2;
        const int stride = CNT_BLOCKS * NTHR;
        int c0 = 0, c2 = 0;
        const int4* l4 = (const int4*)labels;
        #pragma unroll 4
        for (int i = blockIdx.x * NTHR + threadIdx.x; i < n4; i += stride) {
            int4 v = l4[i];
            // Warp-uniform counts via ballot+popc: no serial shuffle chain.
            c0 += __popc(__ballot_sync(0xffffffffu, v.x == 0))
                + __popc(__ballot_sync(0xffffffffu, v.y == 0))
                + __popc(__ballot_sync(0xffffffffu, v.z == 0))
                + __popc(__ballot_sync(0xffffffffu, v.w == 0));
            c2 += __popc(__ballot_sync(0xffffffffu, v.x == 2))
                + __popc(__ballot_sync(0xffffffffu, v.y == 2))
                + __popc(__ballot_sync(0xffffffffu, v.z == 2))
                + __popc(__ballot_sync(0xffffffffu, v.w == 2));
        }
        if (blockIdx.x == 0) {                 // warp-synchronous tail (n%4)
            const int base = n4 << 2;
            for (int i0 = base + (wid << 5); i0 < n; i0 += NTHR) {
                int i = i0 + lane;
                int l = (i < n) ? labels[i] : -1;
                c0 += __popc(__ballot_sync(0xffffffffu, l == 0));
                c2 += __popc(__ballot_sync(0xffffffffu, l == 2));
            }
        }
        __shared__ int s0[NTHR / 32];
        __shared__ int s2[NTHR / 32];
        if (lane == 0) { s0[wid] = c0; s2[wid] = c2; }
        __syncthreads();
        if (threadIdx.x == 0) {
            int t0 = 0, t2v = 0;
            #pragma unroll
            for (int w = 0; w < NTHR / 32; ++w) { t0 += s0[w]; t2v += s2[w]; }
            unsigned long long contrib = (unsigned long long)t0
                                       | ((unsigned long long)t2v << 20)
                                       | DONE_ONE;
            // 4-way-split accumulators: 4 atomics per address instead of 16,
            // chains run in parallel on distinct LTS slices.
            atomicAdd(&g_acc[(blockIdx.x & (N_ACC - 1)) * 32], contrib);
        }
    }
}

extern "C" void kernel_launch(void* const* d_in, const int* in_sizes, int n_in,
                              void* d_out, int out_size) {
    const float* t1 = (const float*)d_in[0];
    const float* t2 = (const float*)d_in[1];
    const int* labels = (const int*)d_in[2];
    float* out = (float*)d_out;

    int n = in_sizes[2];          // 65536 labels
    int d = in_sizes[0] / n;      // 512

    fused_kernel<<<CNT_BLOCKS + 1, NTHR>>>(t1, t2, labels, n, d, out);
}